// round 2
// baseline (speedup 1.0000x reference)
#include <cuda_runtime.h>

#define Bsz 4
#define Hdim 512
#define Tlen 800
#define FFdim 2048
#define NHn 8
#define HEADD 64
#define NLn 6

// ---------------- scratch (device globals; no allocations allowed) ----------
__device__ float g_h[Bsz * Hdim * Tlen];
__device__ float g_q[Bsz * Hdim * Tlen];
__device__ float g_k[Bsz * Hdim * Tlen];
__device__ float g_v[Bsz * Hdim * Tlen];
__device__ float g_ctx[Bsz * Hdim * Tlen];
__device__ float g_y[Bsz * Hdim * Tlen];
__device__ float g_S[Bsz * NHn * Tlen * Tlen];      // 20.48M floats
__device__ float g_mid[Bsz * FFdim * Tlen];
__device__ float g_prior[Bsz * 2 * Hdim * Tlen];

// ---------------- generic 64x64x16 fp32 GEMM body ---------------------------
// C[m,n] = sum_k W[m,k] * X[k,n] + bias[m]   (W: MxK row-major, X: KxN row-major)
__device__ __forceinline__ void gemm_body(
    const float* __restrict__ W, const float* __restrict__ X,
    const float* __restrict__ bias, float* __restrict__ C,
    int M, int K, int N, bool relu)
{
    __shared__ float Ws[16][64];
    __shared__ float Xs[16][68];
    const int tid = threadIdx.x;
    const int tx = tid & 15, ty = tid >> 4;
    const int m0 = blockIdx.y * 64, n0 = blockIdx.x * 64;
    const int wr = tid >> 2, wc = (tid & 3) << 2;
    const int xr = tid >> 4, xc = (tid & 15) << 2;
    float acc[4][4] = {};
    for (int k0 = 0; k0 < K; k0 += 16) {
        float4 w = *reinterpret_cast<const float4*>(W + (size_t)(m0 + wr) * K + k0 + wc);
        Ws[wc + 0][wr] = w.x; Ws[wc + 1][wr] = w.y;
        Ws[wc + 2][wr] = w.z; Ws[wc + 3][wr] = w.w;
        float4 xv = make_float4(0.f, 0.f, 0.f, 0.f);
        if (n0 + xc < N)
            xv = *reinterpret_cast<const float4*>(X + (size_t)(k0 + xr) * N + n0 + xc);
        *reinterpret_cast<float4*>(&Xs[xr][xc]) = xv;
        __syncthreads();
#pragma unroll
        for (int kk = 0; kk < 16; kk++) {
            float4 av = *reinterpret_cast<const float4*>(&Ws[kk][ty << 2]);
            float4 bv = *reinterpret_cast<const float4*>(&Xs[kk][tx << 2]);
            float a[4] = {av.x, av.y, av.z, av.w};
            float b[4] = {bv.x, bv.y, bv.z, bv.w};
#pragma unroll
            for (int i = 0; i < 4; i++)
#pragma unroll
                for (int j = 0; j < 4; j++)
                    acc[i][j] = fmaf(a[i], b[j], acc[i][j]);
        }
        __syncthreads();
    }
#pragma unroll
    for (int i = 0; i < 4; i++) {
        int m = m0 + (ty << 2) + i;
        float bi = bias[m];
#pragma unroll
        for (int j = 0; j < 4; j++) {
            int n = n0 + (tx << 2) + j;
            if (n < N) {
                float v = acc[i][j] + bi;
                if (relu) v = fmaxf(v, 0.f);
                C[(size_t)m * N + n] = v;
            }
        }
    }
}

// ---------------- conv1d (kernel size 3, pad 1) GEMM body --------------------
// C[m,t] = sum_c sum_k W[m,c,k] * (X[c,t+k-1]*mask[t+k-1]) + bias[m]
__device__ __forceinline__ void conv_body(
    const float* __restrict__ W, const float* __restrict__ bias,
    const float* __restrict__ X, const float* __restrict__ mrow,
    float* __restrict__ C, int M, int K, bool relu)
{
    __shared__ float Ws[16][3][64];
    __shared__ float Xs[16][68];   // 66 used
    const int tid = threadIdx.x;
    const int tx = tid & 15, ty = tid >> 4;
    const int m0 = blockIdx.y * 64, n0 = blockIdx.x * 64;
    float acc[4][4] = {};
    for (int k0 = 0; k0 < K; k0 += 16) {
        for (int idx = tid; idx < 16 * 66; idx += 256) {
            int r = idx / 66, c = idx % 66;
            int t = n0 + c - 1;
            float val = 0.f;
            if (t >= 0 && t < Tlen) val = X[(size_t)(k0 + r) * Tlen + t] * mrow[t];
            Xs[r][c] = val;
        }
        for (int idx = tid; idx < 64 * 48; idx += 256) {
            int m = idx & 63;
            int rest = idx >> 6;
            int kk3 = rest % 3, cc = rest / 3;
            Ws[cc][kk3][m] = W[(size_t)(m0 + m) * (K * 3) + (size_t)(k0 + cc) * 3 + kk3];
        }
        __syncthreads();
#pragma unroll
        for (int cc = 0; cc < 16; cc++) {
            float xreg[6];
#pragma unroll
            for (int j = 0; j < 6; j++) xreg[j] = Xs[cc][(tx << 2) + j];
#pragma unroll
            for (int kk = 0; kk < 3; kk++) {
                float4 av = *reinterpret_cast<const float4*>(&Ws[cc][kk][ty << 2]);
                float a[4] = {av.x, av.y, av.z, av.w};
#pragma unroll
                for (int i = 0; i < 4; i++)
#pragma unroll
                    for (int j = 0; j < 4; j++)
                        acc[i][j] = fmaf(a[i], xreg[j + kk], acc[i][j]);
            }
        }
        __syncthreads();
    }
#pragma unroll
    for (int i = 0; i < 4; i++) {
        int m = m0 + (ty << 2) + i;
        float bi = bias[m];
#pragma unroll
        for (int j = 0; j < 4; j++) {
            int n = n0 + (tx << 2) + j;
            if (n < Tlen) {
                float v = acc[i][j] + bi;
                if (relu) v = fmaxf(v, 0.f);
                C[(size_t)m * Tlen + n] = v;
            }
        }
    }
}

// ---------------- kernels ----------------------------------------------------
__global__ void k_init(const float* __restrict__ x, const float* __restrict__ mask)
{
    int i = blockIdx.x * 256 + threadIdx.x;
    if (i < Bsz * Hdim * Tlen) {
        int t = i % Tlen;
        int b = i / (Hdim * Tlen);
        g_h[i] = x[i] * mask[b * Tlen + t];
    }
}

__global__ void k_maskh(const float* __restrict__ mask)
{
    int i = blockIdx.x * 256 + threadIdx.x;
    if (i < Bsz * Hdim * Tlen) {
        int t = i % Tlen;
        int b = i / (Hdim * Tlen);
        g_h[i] *= mask[b * Tlen + t];
    }
}

// fused Q/K/V projections: grid.z = which*4 + batch
__global__ void k_qkv(const float* __restrict__ Wq, const float* __restrict__ Wk,
                      const float* __restrict__ Wv, const float* __restrict__ bq,
                      const float* __restrict__ bk, const float* __restrict__ bv)
{
    int z = blockIdx.z;
    int which = z >> 2, b = z & 3;
    const float* W = (which == 0) ? Wq : (which == 1) ? Wk : Wv;
    const float* bias = (which == 0) ? bq : (which == 1) ? bk : bv;
    float* base = (which == 0) ? g_q : (which == 1) ? g_k : g_v;
    gemm_body(W, g_h + (size_t)b * Hdim * Tlen, bias,
              base + (size_t)b * Hdim * Tlen, Hdim, Hdim, Tlen, false);
}

__global__ void k_wo(const float* __restrict__ W, const float* __restrict__ bias)
{
    int b = blockIdx.z;
    gemm_body(W, g_ctx + (size_t)b * Hdim * Tlen, bias,
              g_y + (size_t)b * Hdim * Tlen, Hdim, Hdim, Tlen, false);
}

__global__ void k_wp(const float* __restrict__ W, const float* __restrict__ bias)
{
    int b = blockIdx.z;
    gemm_body(W, g_h + (size_t)b * Hdim * Tlen, bias,
              g_prior + (size_t)b * 2 * Hdim * Tlen, 2 * Hdim, Hdim, Tlen, false);
}

__global__ void k_conv1(const float* __restrict__ W, const float* __restrict__ bias,
                        const float* __restrict__ mask)
{
    int b = blockIdx.z;
    conv_body(W, bias, g_h + (size_t)b * Hdim * Tlen, mask + b * Tlen,
              g_mid + (size_t)b * FFdim * Tlen, FFdim, Hdim, true);
}

__global__ void k_conv2(const float* __restrict__ W, const float* __restrict__ bias,
                        const float* __restrict__ mask)
{
    int b = blockIdx.z;
    conv_body(W, bias, g_mid + (size_t)b * FFdim * Tlen, mask + b * Tlen,
              g_y + (size_t)b * Hdim * Tlen, Hdim, FFdim, false);
}

// scores: S[t,s] = 0.125*(q[t]·k[s] + band) with mask override.
__global__ void k_scores(const float* __restrict__ ek, const float* __restrict__ mask)
{
    __shared__ float Qs[64][64];
    __shared__ float Ks[64][64];
    int z = blockIdx.z;
    int b = z >> 3, h = z & 7;
    const float* Q = g_q + ((size_t)b * Hdim + h * HEADD) * Tlen;
    const float* Kp = g_k + ((size_t)b * Hdim + h * HEADD) * Tlen;
    float* S = g_S + (size_t)z * Tlen * Tlen;
    const float* mrow = mask + b * Tlen;
    int t0 = blockIdx.y * 64, s0 = blockIdx.x * 64;
    int tid = threadIdx.x, tx = tid & 15, ty = tid >> 4;
    for (int idx = tid; idx < 64 * 64; idx += 256) {
        int r = idx >> 6, c = idx & 63;
        int t = t0 + c;
        Qs[r][c] = (t < Tlen) ? Q[(size_t)r * Tlen + t] : 0.f;
        int s = s0 + c;
        Ks[r][c] = (s < Tlen) ? Kp[(size_t)r * Tlen + s] : 0.f;
    }
    __syncthreads();
    float acc[4][4] = {};
#pragma unroll 16
    for (int kk = 0; kk < 64; kk++) {
        float4 qv = *reinterpret_cast<const float4*>(&Qs[kk][ty << 2]);
        float4 kv = *reinterpret_cast<const float4*>(&Ks[kk][tx << 2]);
        float a[4] = {qv.x, qv.y, qv.z, qv.w};
        float c4[4] = {kv.x, kv.y, kv.z, kv.w};
#pragma unroll
        for (int i = 0; i < 4; i++)
#pragma unroll
            for (int j = 0; j < 4; j++)
                acc[i][j] = fmaf(a[i], c4[j], acc[i][j]);
    }
    const float scale = 0.125f;
#pragma unroll
    for (int i = 0; i < 4; i++) {
        int t = t0 + (ty << 2) + i;
        if (t >= Tlen) continue;
#pragma unroll
        for (int j = 0; j < 4; j++) {
            int s = s0 + (tx << 2) + j;
            if (s >= Tlen) continue;
            float v = acc[i][j];
            int delta = s - t;
            if (delta >= -4 && delta <= 4) {
                const float* e = ek + (delta + 4) * HEADD;
                float r = 0.f;
                for (int d = 0; d < 64; d++) r += Qs[d][(ty << 2) + i] * e[d];
                v += r;
            }
            v *= scale;
            if (mrow[t] == 0.f || mrow[s] == 0.f) v = -1e4f;
            S[(size_t)t * Tlen + s] = v;
        }
    }
}

__global__ void k_softmax()
{
    size_t row = blockIdx.x;
    float* p = g_S + row * Tlen;
    __shared__ float red[256];
    int tid = threadIdx.x;
    float v[4];
    float mx = -1e30f;
#pragma unroll
    for (int i = 0; i < 4; i++) {
        int c = tid + (i << 8);
        v[i] = (c < Tlen) ? p[c] : -1e30f;
        mx = fmaxf(mx, v[i]);
    }
    red[tid] = mx; __syncthreads();
    for (int s = 128; s > 0; s >>= 1) {
        if (tid < s) red[tid] = fmaxf(red[tid], red[tid + s]);
        __syncthreads();
    }
    mx = red[0]; __syncthreads();
    float sum = 0.f;
#pragma unroll
    for (int i = 0; i < 4; i++) {
        int c = tid + (i << 8);
        if (c < Tlen) { v[i] = __expf(v[i] - mx); sum += v[i]; }
    }
    red[tid] = sum; __syncthreads();
    for (int s = 128; s > 0; s >>= 1) {
        if (tid < s) red[tid] += red[tid + s];
        __syncthreads();
    }
    float inv = 1.f / red[0];
#pragma unroll
    for (int i = 0; i < 4; i++) {
        int c = tid + (i << 8);
        if (c < Tlen) p[c] = v[i] * inv;
    }
}

// ctx[d,t] = sum_s V[d,s] * P[t,s]
__global__ void k_attnout()
{
    __shared__ float Vs[16][68];
    __shared__ float Ps[16][68];
    int z = blockIdx.z;
    int b = z >> 3, h = z & 7;
    const float* V = g_v + ((size_t)b * Hdim + h * HEADD) * Tlen;
    const float* P = g_S + (size_t)z * Tlen * Tlen;
    float* O = g_ctx + ((size_t)b * Hdim + h * HEADD) * Tlen;
    int n0 = blockIdx.x * 64;
    int tid = threadIdx.x, tx = tid & 15, ty = tid >> 4;
    float acc[4][4] = {};
    for (int s0 = 0; s0 < Tlen; s0 += 16) {
        {
            int d = tid >> 2, sc = (tid & 3) << 2;
            float4 vv = *reinterpret_cast<const float4*>(V + (size_t)d * Tlen + s0 + sc);
            Vs[sc + 0][d] = vv.x; Vs[sc + 1][d] = vv.y;
            Vs[sc + 2][d] = vv.z; Vs[sc + 3][d] = vv.w;
        }
        {
            int tt = tid >> 2, sc = (tid & 3) << 2;
            float4 pv = make_float4(0.f, 0.f, 0.f, 0.f);
            if (n0 + tt < Tlen)
                pv = *reinterpret_cast<const float4*>(P + (size_t)(n0 + tt) * Tlen + s0 + sc);
            Ps[sc + 0][tt] = pv.x; Ps[sc + 1][tt] = pv.y;
            Ps[sc + 2][tt] = pv.z; Ps[sc + 3][tt] = pv.w;
        }
        __syncthreads();
#pragma unroll
        for (int kk = 0; kk < 16; kk++) {
            float4 av = *reinterpret_cast<const float4*>(&Vs[kk][ty << 2]);
            float4 bv = *reinterpret_cast<const float4*>(&Ps[kk][tx << 2]);
            float a[4] = {av.x, av.y, av.z, av.w};
            float c4[4] = {bv.x, bv.y, bv.z, bv.w};
#pragma unroll
            for (int i = 0; i < 4; i++)
#pragma unroll
                for (int j = 0; j < 4; j++)
                    acc[i][j] = fmaf(a[i], c4[j], acc[i][j]);
        }
        __syncthreads();
    }
#pragma unroll
    for (int i = 0; i < 4; i++) {
        int d = (ty << 2) + i;
#pragma unroll
        for (int j = 0; j < 4; j++) {
            int t = n0 + (tx << 2) + j;
            if (t < Tlen) O[(size_t)d * Tlen + t] = acc[i][j];
        }
    }
}

// ctx[d,t] += sum_j P[t, t+j-4] * ev[j,d]
__global__ void k_bandout(const float* __restrict__ ev)
{
    int t = blockIdx.x;
    int z = blockIdx.y;
    int b = z >> 3, h = z & 7;
    const float* P = g_S + (size_t)z * Tlen * Tlen + (size_t)t * Tlen;
    float* O = g_ctx + ((size_t)b * Hdim + h * HEADD) * Tlen;
    __shared__ float p9[9];
    if (threadIdx.x < 9) {
        int s = t + (int)threadIdx.x - 4;
        p9[threadIdx.x] = (s >= 0 && s < Tlen) ? P[s] : 0.f;
    }
    __syncthreads();
    int d = threadIdx.x;
    float r = 0.f;
#pragma unroll
    for (int j = 0; j < 9; j++) r = fmaf(p9[j], ev[j * HEADD + d], r);
    O[(size_t)d * Tlen + t] += r;
}

// h = LayerNorm_c(h + y*(ymask or 1)) * g + beta ; writes back into g_h
__global__ void k_addln(const float* __restrict__ gw, const float* __restrict__ bw,
                        const float* __restrict__ ymask)
{
    int b = blockIdx.y;
    int t = blockIdx.x * 32 + threadIdx.x;
    int cg = threadIdx.y;               // 0..7, each covers 64 channels
    float* H = g_h + (size_t)b * Hdim * Tlen;
    const float* Y = g_y + (size_t)b * Hdim * Tlen;
    float mfac = ymask ? ymask[b * Tlen + t] : 1.f;
    float z[64];
    float s = 0.f, sq = 0.f;
#pragma unroll
    for (int i = 0; i < 64; i++) {
        int c = cg * 64 + i;
        float val = H[(size_t)c * Tlen + t] + Y[(size_t)c * Tlen + t] * mfac;
        z[i] = val;
        s += val;
        sq += val * val;
    }
    __shared__ float ss[8][32], ssq[8][32];
    ss[cg][threadIdx.x] = s;
    ssq[cg][threadIdx.x] = sq;
    __syncthreads();
    if (cg == 0) {
        float S = 0.f, SQ = 0.f;
#pragma unroll
        for (int k = 0; k < 8; k++) { S += ss[k][threadIdx.x]; SQ += ssq[k][threadIdx.x]; }
        float mean = S * (1.f / 512.f);
        float var = SQ * (1.f / 512.f) - mean * mean;
        ss[0][threadIdx.x] = mean;
        ssq[0][threadIdx.x] = rsqrtf(var + 1e-5f);
    }
    __syncthreads();
    float mean = ss[0][threadIdx.x];
    float rstd = ssq[0][threadIdx.x];
#pragma unroll
    for (int i = 0; i < 64; i++) {
        int c = cg * 64 + i;
        H[(size_t)c * Tlen + t] = (z[i] - mean) * rstd * gw[c] + bw[c];
    }
}

// out layout: mu_p (all batches) then logs_p (all batches)
__global__ void k_final(const float* __restrict__ mask, float* __restrict__ out)
{
    int i = blockIdx.x * 256 + threadIdx.x;
    if (i < Bsz * 2 * Hdim * Tlen) {
        int t = i % Tlen;
        int r = i / Tlen;
        int o = r % (2 * Hdim);
        int b = r / (2 * Hdim);
        float v = g_prior[i] * mask[b * Tlen + t];
        size_t dst;
        if (o < Hdim) dst = ((size_t)b * Hdim + o) * Tlen + t;
        else dst = (size_t)Bsz * Hdim * Tlen + ((size_t)b * Hdim + (o - Hdim)) * Tlen + t;
        out[dst] = v;
    }
}

// ---------------- orchestration ---------------------------------------------
extern "C" void kernel_launch(void* const* d_in, const int* in_sizes, int n_in,
                              void* d_out, int out_size)
{
    const float* x    = (const float*)d_in[0];
    const float* mask = (const float*)d_in[1];
    const float* Wq   = (const float*)d_in[2];
    const float* bq   = (const float*)d_in[3];
    const float* Wk   = (const float*)d_in[4];
    const float* bk   = (const float*)d_in[5];
    const float* Wv   = (const float*)d_in[6];
    const float* bv   = (const float*)d_in[7];
    const float* Wo   = (const float*)d_in[8];
    const float* bo   = (const float*)d_in[9];
    const float* erk  = (const float*)d_in[10];
    const float* erv  = (const float*)d_in[11];
    const float* g1   = (const float*)d_in[12];
    const float* b1   = (const float*)d_in[13];
    const float* g2   = (const float*)d_in[14];
    const float* b2   = (const float*)d_in[15];
    const float* Wf1  = (const float*)d_in[16];
    const float* bf1  = (const float*)d_in[17];
    const float* Wf2  = (const float*)d_in[18];
    const float* bf2  = (const float*)d_in[19];
    const float* Wp   = (const float*)d_in[20];
    const float* bp   = (const float*)d_in[21];
    float* out = (float*)d_out;

    const int nt = (Tlen + 63) / 64;    // 13
    const int nElem = Bsz * Hdim * Tlen;

    k_init<<<(nElem + 255) / 256, 256>>>(x, mask);

    for (int L = 0; L < NLn; L++) {
        const float* Wq_ = Wq + (size_t)L * Hdim * Hdim;
        const float* Wk_ = Wk + (size_t)L * Hdim * Hdim;
        const float* Wv_ = Wv + (size_t)L * Hdim * Hdim;
        const float* Wo_ = Wo + (size_t)L * Hdim * Hdim;
        const float* bq_ = bq + (size_t)L * Hdim;
        const float* bk_ = bk + (size_t)L * Hdim;
        const float* bv_ = bv + (size_t)L * Hdim;
        const float* bo_ = bo + (size_t)L * Hdim;
        const float* ek_ = erk + (size_t)L * 9 * HEADD;
        const float* ev_ = erv + (size_t)L * 9 * HEADD;
        const float* g1_ = g1 + (size_t)L * Hdim;
        const float* b1_ = b1 + (size_t)L * Hdim;
        const float* g2_ = g2 + (size_t)L * Hdim;
        const float* b2_ = b2 + (size_t)L * Hdim;
        const float* Wf1_ = Wf1 + (size_t)L * FFdim * Hdim * 3;
        const float* bf1_ = bf1 + (size_t)L * FFdim;
        const float* Wf2_ = Wf2 + (size_t)L * Hdim * FFdim * 3;
        const float* bf2_ = bf2 + (size_t)L * Hdim;

        k_qkv<<<dim3(nt, Hdim / 64, 12), 256>>>(Wq_, Wk_, Wv_, bq_, bk_, bv_);
        k_scores<<<dim3(nt, nt, Bsz * NHn), 256>>>(ek_, mask);
        k_softmax<<<Bsz * NHn * Tlen, 256>>>();
        k_attnout<<<dim3(nt, 1, Bsz * NHn), 256>>>();
        k_bandout<<<dim3(Tlen, Bsz * NHn), 64>>>(ev_);
        k_wo<<<dim3(nt, Hdim / 64, Bsz), 256>>>(Wo_, bo_);
        k_addln<<<dim3(Tlen / 32, Bsz), dim3(32, 8)>>>(g1_, b1_, nullptr);
        k_conv1<<<dim3(nt, FFdim / 64, Bsz), 256>>>(Wf1_, bf1_, mask);
        k_conv2<<<dim3(nt, Hdim / 64, Bsz), 256>>>(Wf2_, bf2_, mask);
        k_addln<<<dim3(Tlen / 32, Bsz), dim3(32, 8)>>>(g2_, b2_, mask);
    }

    k_maskh<<<(nElem + 255) / 256, 256>>>(mask);
    k_wp<<<dim3(nt, 2 * Hdim / 64, Bsz), 256>>>(Wp, bp);
    k_final<<<(Bsz * 2 * Hdim * Tlen + 255) / 256, 256>>>(mask, out);
}